// round 12
// baseline (speedup 1.0000x reference)
#include <cuda_runtime.h>
#include <cstdint>
#include <cstddef>

#define NMAX 100000
#define EMAX 800000
#define HIDD 96
#define SCAN_BLK 1024

// ---------------- scratch (no allocations allowed) ----------------
__device__ __align__(16) float g_dinv[NMAX];
__device__ __align__(16) float g_hA[(size_t)NMAX * HIDD];   // GEMM out, prescaled by dinv[row]
__device__ __align__(16) float g_agg[(size_t)NMAX * HIDD];  // gather output (pre-BN)
__device__ __align__(16) float g_stats[2 * 192];            // per-layer [sum(96) | sumsq(96)]
__device__ int g_cnt[NMAX];
__device__ int g_off[NMAX + 1];
__device__ int g_cur[NMAX];
__device__ int g_srcs[EMAX];
__device__ int g_pub[128];                                  // decoupled-scan publish slots

// ---------------- zero everything that needs zeroing (one kernel) ----------------
__global__ void k_zero(int N, int nb) {
    int i = blockIdx.x * blockDim.x + threadIdx.x;
    if (i < N) { g_cnt[i] = 0; g_cur[i] = 0; }
    if (i < nb) g_pub[i] = 0;
    if (i < 2 * 192) g_stats[i] = 0.f;
}
__global__ void k_hist(const int* __restrict__ dst, int E) {
    int e = blockIdx.x * blockDim.x + threadIdx.x;
    if (e < E) atomicAdd(&g_cnt[dst[e]], 1);
}

// ---------------- fused exclusive scan + dinv (decoupled raking) ----------------
__global__ __launch_bounds__(SCAN_BLK)
void k_scan(int N) {
    __shared__ int s[SCAN_BLK];
    __shared__ int wsum[32];
    __shared__ int base_sh;
    const int tid = threadIdx.x;
    const int b = blockIdx.x;
    const int i = b * SCAN_BLK + tid;
    const int myc = (i < N) ? g_cnt[i] : 0;

    s[tid] = myc;
    __syncthreads();
#pragma unroll
    for (int o = 1; o < SCAN_BLK; o <<= 1) {
        int t = (tid >= o) ? s[tid - o] : 0;
        __syncthreads();
        s[tid] += t;
        __syncthreads();
    }

    if (tid == SCAN_BLK - 1) atomicExch(&g_pub[b], s[SCAN_BLK - 1] + 1);

    int p = 0;
    if (tid < b) {
        int v;
        do { v = atomicAdd(&g_pub[tid], 0); } while (v == 0);
        p = v - 1;
    }
#pragma unroll
    for (int o = 16; o > 0; o >>= 1) p += __shfl_xor_sync(0xFFFFFFFFu, p, o);
    if ((tid & 31) == 0) wsum[tid >> 5] = p;
    __syncthreads();
    if (tid == 0) {
        int a = 0;
#pragma unroll
        for (int wgi = 0; wgi < 32; wgi++) a += wsum[wgi];
        base_sh = a;
    }
    __syncthreads();
    const int base = base_sh;

    if (i < N) {
        g_off[i + 1] = base + s[tid];
        g_dinv[i] = rsqrtf((float)(myc + 1));   // +1 self loop
    }
    if (b == 0 && tid == 0) g_off[0] = 0;
}

__global__ void k_reorder(const int* __restrict__ src, const int* __restrict__ dst, int E) {
    int e = blockIdx.x * blockDim.x + threadIdx.x;
    if (e < E) {
        int d = dst[e];
        int pos = g_off[d] + atomicAdd(&g_cur[d], 1);
        g_srcs[pos] = src[e];
    }
}

// ---------------- GEMM: g_hA[N,OUT] = dinv[row] * (act(X)[N,K] @ W[K,OUT]) ----------------
// K staged in 32-col chunks: X-tile (rows x 32) and W-chunk (32 x OUT) both in
// SMEM, loaded coalesced. MODE 0: X=ptr, no act. MODE 1/2: X=g_agg with fused
// BN(stats MODE-1)+ReLU applied at the staging load.
__device__ __forceinline__ float f4c(const float4& v, int kk) {
    switch (kk) { case 0: return v.x; case 1: return v.y; case 2: return v.z; default: return v.w; }
}

template <int K, int OUT, int RY, int MODE>
__global__ __launch_bounds__((OUT / 8) * RY)
void gemm_kernel(const float* __restrict__ Xarg, const float* __restrict__ W,
                 const float* __restrict__ gamma, const float* __restrict__ beta, int N) {
    constexpr int CG = OUT / 8;        // thread col-groups (8 cols each)
    constexpr int C4 = OUT / 4;        // float4s per W row
    constexpr int NT = CG * RY;        // threads
    constexpr int ROWS = RY * 8;       // rows per block
    constexpr int NCH = K / 32;        // K chunks
    constexpr int XLD = 9;             // Xs row stride in float4 (bank-skewed)
    constexpr int SAB = (MODE != 0) ? K : 1;

    __shared__ float4 Ws[32 * C4];     // current W chunk
    __shared__ float4 Xs[ROWS * XLD];  // current X chunk (8 f4 used per row)
    __shared__ float sa[SAB];
    __shared__ float sc[SAB];

    const int tid = threadIdx.y * CG + threadIdx.x;
    if (MODE) {
        const float* st = g_stats + (MODE - 1) * 192;
        for (int f = tid; f < K; f += NT) {
            float invN = 1.0f / (float)N;
            float mu = st[f] * invN;
            float var = st[96 + f] * invN - mu * mu;
            float a = gamma[f] * rsqrtf(var + 1e-5f);
            sa[f] = a;
            sc[f] = beta[f] - mu * a;
        }
    }

    const float* X = MODE ? (const float*)g_agg : Xarg;
    const float4* X4 = (const float4*)X;
    const float4* W4 = (const float4*)W;
    constexpr int ldx = K / 4;

    const int c = threadIdx.x;
    const int blockRow = blockIdx.x * ROWS;
    const int r0 = blockRow + threadIdx.y * 8;

    float4 acc[8][2];
#pragma unroll
    for (int r = 0; r < 8; r++) {
        acc[r][0] = make_float4(0.f, 0.f, 0.f, 0.f);
        acc[r][1] = make_float4(0.f, 0.f, 0.f, 0.f);
    }

    for (int kc = 0; kc < NCH; kc++) {
        __syncthreads();
        // stage W chunk: rows kc*32 .. kc*32+31, coalesced
        for (int i = tid; i < 32 * C4; i += NT)
            Ws[i] = W4[(size_t)(kc * 32 + i / C4) * C4 + (i % C4)];
        // stage X chunk: ROWS x 32 cols, coalesced (8 consecutive f4 per row)
        for (int i = tid; i < ROWS * 8; i += NT) {
            int rl = i >> 3;
            int j = i & 7;
            int grow = blockRow + rl;
            float4 v = (grow < N) ? X4[(size_t)grow * ldx + kc * 8 + j]
                                  : make_float4(0.f, 0.f, 0.f, 0.f);
            if (MODE) {
                float4 ba = ((const float4*)sa)[kc * 8 + j];
                float4 bc = ((const float4*)sc)[kc * 8 + j];
                v.x = fmaxf(ba.x * v.x + bc.x, 0.f);
                v.y = fmaxf(ba.y * v.y + bc.y, 0.f);
                v.z = fmaxf(ba.z * v.z + bc.z, 0.f);
                v.w = fmaxf(ba.w * v.w + bc.w, 0.f);
            }
            Xs[rl * XLD + j] = v;
        }
        __syncthreads();

#pragma unroll
        for (int k4 = 0; k4 < 8; k4++) {
            float4 xr[8];
#pragma unroll
            for (int r = 0; r < 8; r++)
                xr[r] = Xs[(threadIdx.y * 8 + r) * XLD + k4];
#pragma unroll
            for (int kk = 0; kk < 4; kk++) {
                float4 w0 = Ws[(k4 * 4 + kk) * C4 + 2 * c];
                float4 w1 = Ws[(k4 * 4 + kk) * C4 + 2 * c + 1];
#pragma unroll
                for (int r = 0; r < 8; r++) {
                    float xv = f4c(xr[r], kk);
                    acc[r][0].x += xv * w0.x; acc[r][0].y += xv * w0.y;
                    acc[r][0].z += xv * w0.z; acc[r][0].w += xv * w0.w;
                    acc[r][1].x += xv * w1.x; acc[r][1].y += xv * w1.y;
                    acc[r][1].z += xv * w1.z; acc[r][1].w += xv * w1.w;
                }
            }
        }
    }

    float4* Y4 = (float4*)g_hA;
#pragma unroll
    for (int r = 0; r < 8; r++) {
        int row = r0 + r;
        if (row < N) {
            float dr = g_dinv[row];
            float4 a0 = acc[r][0], a1 = acc[r][1];
            a0.x *= dr; a0.y *= dr; a0.z *= dr; a0.w *= dr;
            a1.x *= dr; a1.y *= dr; a1.z *= dr; a1.w *= dr;
            Y4[(size_t)row * C4 + 2 * c]     = a0;
            Y4[(size_t)row * C4 + 2 * c + 1] = a1;
        }
    }
}

// ---------------- gather96: warp per node, CSR in-edges ----------------
__global__ __launch_bounds__(256)
void gather96_kernel(const float* __restrict__ bias, int layer, int N) {
    __shared__ float sred[192];
    const int tid = threadIdx.x;
    for (int i = tid; i < 192; i += 256) sred[i] = 0.f;
    __syncthreads();

    const int lane = tid & 31;
    const int w = tid >> 5;
    const int c0 = lane, c1 = lane + 32, c2 = lane + 64;
    const float b0 = bias[c0], b1 = bias[c1], b2 = bias[c2];
    const int nwarps = gridDim.x * 8;

    float s0 = 0.f, s1 = 0.f, s2 = 0.f;
    float q0 = 0.f, q1 = 0.f, q2 = 0.f;

    for (int d = blockIdx.x * 8 + w; d < N; d += nwarps) {
        const int beg = g_off[d];
        const int end = g_off[d + 1];
        float a0 = 0.f, a1 = 0.f, a2 = 0.f;
        int j = beg;
        for (; j + 3 < end; j += 4) {
            int sa = g_srcs[j], sb = g_srcs[j + 1], sc = g_srcs[j + 2], se = g_srcs[j + 3];
            const float* ha = g_hA + (size_t)sa * 96;
            const float* hb = g_hA + (size_t)sb * 96;
            const float* hc = g_hA + (size_t)sc * 96;
            const float* he = g_hA + (size_t)se * 96;
            float x0a = ha[c0], x1a = ha[c1], x2a = ha[c2];
            float x0b = hb[c0], x1b = hb[c1], x2b = hb[c2];
            float x0c = hc[c0], x1c = hc[c1], x2c = hc[c2];
            float x0e = he[c0], x1e = he[c1], x2e = he[c2];
            a0 += (x0a + x0b) + (x0c + x0e);
            a1 += (x1a + x1b) + (x1c + x1e);
            a2 += (x2a + x2b) + (x2c + x2e);
        }
        for (; j < end; j++) {
            int sa = g_srcs[j];
            const float* ha = g_hA + (size_t)sa * 96;
            a0 += ha[c0]; a1 += ha[c1]; a2 += ha[c2];
        }
        const float dd = g_dinv[d];
        const float* hd = g_hA + (size_t)d * 96;
        a0 += hd[c0]; a1 += hd[c1]; a2 += hd[c2];
        float v0 = dd * a0 + b0;
        float v1 = dd * a1 + b1;
        float v2 = dd * a2 + b2;
        float* od = g_agg + (size_t)d * 96;
        od[c0] = v0; od[c1] = v1; od[c2] = v2;
        s0 += v0; s1 += v1; s2 += v2;
        q0 += v0 * v0; q1 += v1 * v1; q2 += v2 * v2;
    }

    atomicAdd(&sred[c0], s0); atomicAdd(&sred[c1], s1); atomicAdd(&sred[c2], s2);
    atomicAdd(&sred[96 + c0], q0); atomicAdd(&sred[96 + c1], q1); atomicAdd(&sred[96 + c2], q2);
    __syncthreads();
    float* st = g_stats + layer * 192;
    for (int i = tid; i < 192; i += 256) atomicAdd(&st[i], sred[i]);
}

// ---------------- layer-3: gather(32) + log_softmax, warp per node ----------------
__global__ __launch_bounds__(256)
void gather32_softmax_kernel(const float* __restrict__ b3, float* __restrict__ out, int N) {
    int d = blockIdx.x * 8 + (threadIdx.x >> 5);
    int lane = threadIdx.x & 31;
    if (d >= N) return;
    const int beg = g_off[d];
    const int end = g_off[d + 1];
    float a = 0.f;
    int j = beg;
    for (; j + 3 < end; j += 4) {
        int sa = g_srcs[j], sb = g_srcs[j + 1], sc = g_srcs[j + 2], se = g_srcs[j + 3];
        float xa = g_hA[(size_t)sa * 32 + lane];
        float xb = g_hA[(size_t)sb * 32 + lane];
        float xc = g_hA[(size_t)sc * 32 + lane];
        float xe = g_hA[(size_t)se * 32 + lane];
        a += (xa + xb) + (xc + xe);
    }
    for (; j < end; j++) {
        int sa = g_srcs[j];
        a += g_hA[(size_t)sa * 32 + lane];
    }
    float dd = g_dinv[d];
    a += g_hA[(size_t)d * 32 + lane];
    float v = dd * a + b3[lane];
    float m = v;
#pragma unroll
    for (int o = 16; o > 0; o >>= 1) m = fmaxf(m, __shfl_xor_sync(0xFFFFFFFFu, m, o));
    float s = expf(v - m);
#pragma unroll
    for (int o = 16; o > 0; o >>= 1) s += __shfl_xor_sync(0xFFFFFFFFu, s, o);
    out[(size_t)d * 32 + lane] = v - m - logf(s);
}

// ---------------- host ----------------
extern "C" void kernel_launch(void* const* d_in, const int* in_sizes, int n_in,
                              void* d_out, int out_size) {
    const float* x  = (const float*)d_in[0];
    const int* ei   = (const int*)d_in[1];   // int32 in practice (JAX x64 disabled)
    const float* W1 = (const float*)d_in[2];
    const float* b1 = (const float*)d_in[3];
    const float* W2 = (const float*)d_in[4];
    const float* b2 = (const float*)d_in[5];
    const float* W3 = (const float*)d_in[6];
    const float* b3 = (const float*)d_in[7];
    const float* g1 = (const float*)d_in[8];
    const float* be1 = (const float*)d_in[9];
    const float* g2 = (const float*)d_in[10];
    const float* be2 = (const float*)d_in[11];
    float* out = (float*)d_out;

    int N = in_sizes[0] / 128;
    int E = in_sizes[1] / 2;
    const int* src = ei;
    const int* dst = ei + E;
    int nb = (N + SCAN_BLK - 1) / SCAN_BLK;

    // --- CSR build ---
    k_zero<<<(N + 1023) / 1024, 1024>>>(N, nb);
    k_hist<<<(E + 255) / 256, 256>>>(dst, E);
    k_scan<<<nb, SCAN_BLK>>>(N);
    gemm_kernel<128, 96, 16, 0><<<(N + 127) / 128, dim3(12, 16)>>>(x, W1, nullptr, nullptr, N);
    k_reorder<<<(E + 255) / 256, 256>>>(src, dst, E);

    // --- layer 1 ---
    gather96_kernel<<<592, 256>>>(b1, 0, N);

    // --- layer 2 (BN+ReLU fused into GEMM X staging) ---
    gemm_kernel<96, 96, 16, 1><<<(N + 127) / 128, dim3(12, 16)>>>(nullptr, W2, g1, be1, N);
    gather96_kernel<<<592, 256>>>(b2, 1, N);

    // --- layer 3 (BN+ReLU fused), then gather + log_softmax ---
    gemm_kernel<96, 32, 32, 2><<<(N + 255) / 256, dim3(4, 32)>>>(nullptr, W3, g2, be2, N);
    gather32_softmax_kernel<<<(N + 7) / 8, 256>>>(b3, out, N);
}